// round 1
// baseline (speedup 1.0000x reference)
#include <cuda_runtime.h>

// CrossFrameAttention: out = softmax((xWq)(ctxWk)^T * d^-0.5) (ctxWv) Wo + bo
// B=4, N=M=2048, DIM=512, H=8, Dh=64. fp32 throughout (round-0 baseline).

#define HEADS 8
#define DH 64
#define DIMW 512
#define BATCH 4
#define SEQ 2048
#define ROWS_TOTAL (BATCH * SEQ)   // 8192
#define SCALE 0.125f               // 64^-0.5

// ---------------- scratch (device globals: no allocations allowed) ----------
__device__ float g_Qt[BATCH * HEADS * DH * SEQ];   // [bh][d][n]  16.8 MB
__device__ float g_Kt[BATCH * HEADS * DH * SEQ];   // [bh][d][m]  16.8 MB
__device__ float g_V [BATCH * HEADS * SEQ * DH];   // [bh][m][d]  16.8 MB
__device__ float g_AO[ROWS_TOTAL * DIMW];          // [b*n][h*d]  16.8 MB

// Store modes for the generic 512-K GEMM
#define MODE_T 0   // out[((b*H + c/64)*64 + c%64)*SEQ + n]   (transposed head layout, Q/K)
#define MODE_V 1   // out[((b*H + c/64)*SEQ + n)*64 + c%64]   (split-head row-major, V)
#define MODE_P 2   // out[r*512 + c] + bias[c]                (plain, final projection)

// ---------------- generic GEMM: C[R,512] = A[R,512] @ W[512,512] ------------
// 64x64 tile, BK=16, 256 threads, 4x4 micro-tile.
__global__ __launch_bounds__(256) void gemm512k(
    const float* __restrict__ A, const float* __restrict__ W,
    float* __restrict__ out, const float* __restrict__ bias, int mode)
{
    __shared__ float AsT[16][68];   // transposed A tile, padded (bank split for ty pair)
    __shared__ float Bs [16][64];

    int tid = threadIdx.x;
    int tx = tid & 15, ty = tid >> 4;
    int row0 = blockIdx.x << 6;
    int col0 = blockIdx.y << 6;

    float acc[4][4] = {};

    int lr  = tid >> 2;            // 0..63 : A tile row
    int lk4 = (tid & 3) << 2;      // 0,4,8,12 : A tile k (float4)
    int bk  = tid >> 4;            // 0..15 : W tile k
    int bc4 = (tid & 15) << 2;     // 0..60 : W tile col (float4)

    const float* Ap = A + (row0 + lr) * DIMW + lk4;
    const float* Wp = W + bk * DIMW + col0 + bc4;

    for (int k0 = 0; k0 < DIMW; k0 += 16) {
        float4 a4 = *(const float4*)(Ap + k0);
        AsT[lk4 + 0][lr] = a4.x;
        AsT[lk4 + 1][lr] = a4.y;
        AsT[lk4 + 2][lr] = a4.z;
        AsT[lk4 + 3][lr] = a4.w;
        *(float4*)&Bs[bk][bc4] = *(const float4*)(Wp + k0 * DIMW);
        __syncthreads();

        #pragma unroll
        for (int k = 0; k < 16; k++) {
            float a[4], b[4];
            *(float4*)a = *(float4*)&AsT[k][ty << 2];
            *(float4*)b = *(float4*)&Bs [k][tx << 2];
            #pragma unroll
            for (int i = 0; i < 4; i++)
                #pragma unroll
                for (int j = 0; j < 4; j++)
                    acc[i][j] = fmaf(a[i], b[j], acc[i][j]);
        }
        __syncthreads();
    }

    #pragma unroll
    for (int i = 0; i < 4; i++) {
        int r = row0 + (ty << 2) + i;
        int b = r >> 11;           // r / 2048
        int n = r & 2047;
        #pragma unroll
        for (int j = 0; j < 4; j++) {
            int c = col0 + (tx << 2) + j;
            float v = acc[i][j];
            if (mode == MODE_T) {
                out[(((b * HEADS + (c >> 6)) << 6) + (c & 63)) * SEQ + n] = v;
            } else if (mode == MODE_V) {
                out[(((b * HEADS + (c >> 6)) * SEQ + n) << 6) + (c & 63)] = v;
            } else {
                out[r * DIMW + c] = v + bias[c];
            }
        }
    }
}

// ---------------- flash attention: per (bh, 64-row query tile) --------------
// smem: QsT[64][68] + KsT[64][68] (reused as P) + Vs[64][68] = 52224 B dynamic.
__global__ __launch_bounds__(256) void attn_kernel(
    const float* __restrict__ Qt, const float* __restrict__ Kt,
    const float* __restrict__ V, float* __restrict__ AO)
{
    extern __shared__ float sm[];
    float (*QsT)[68] = (float(*)[68])(sm);
    float (*KsT)[68] = (float(*)[68])(sm + 64 * 68);       // also holds P tile
    float (*Vs )[68] = (float(*)[68])(sm + 2 * 64 * 68);

    int tid = threadIdx.x;
    int tx = tid & 15, ty = tid >> 4;
    int bh = blockIdx.y;
    int n0 = blockIdx.x << 6;

    const float* Qb = Qt + bh * DH * SEQ;
    const float* Kb = Kt + bh * DH * SEQ;
    const float* Vb = V  + bh * SEQ * DH;

    // Q tile: already [d][n] in global -> direct coalesced float4 loads
    #pragma unroll
    for (int it = 0; it < 4; it++) {
        int idx = (it << 8) + tid;
        int d  = idx >> 4;
        int r4 = (idx & 15) << 2;
        *(float4*)&QsT[d][r4] = *(const float4*)&Qb[d * SEQ + n0 + r4];
    }

    float m[4], l[4], o[4][4];
    #pragma unroll
    for (int i = 0; i < 4; i++) {
        m[i] = -1e30f; l[i] = 0.f;
        #pragma unroll
        for (int j = 0; j < 4; j++) o[i][j] = 0.f;
    }

    for (int m0 = 0; m0 < SEQ; m0 += 64) {
        #pragma unroll
        for (int it = 0; it < 4; it++) {
            int idx = (it << 8) + tid;
            int a  = idx >> 4;
            int b4 = (idx & 15) << 2;
            *(float4*)&KsT[a][b4] = *(const float4*)&Kb[a * SEQ + m0 + b4];
            *(float4*)&Vs [a][b4] = *(const float4*)&Vb[((m0 + a) << 6) + b4];
        }
        __syncthreads();

        // S = Q @ K^T  (both operands k-major in smem -> LDS.128 everywhere)
        float s[4][4] = {};
        #pragma unroll
        for (int kd = 0; kd < 64; kd++) {
            float a[4], b[4];
            *(float4*)a = *(float4*)&QsT[kd][ty << 2];
            *(float4*)b = *(float4*)&KsT[kd][tx << 2];
            #pragma unroll
            for (int i = 0; i < 4; i++)
                #pragma unroll
                for (int j = 0; j < 4; j++)
                    s[i][j] = fmaf(a[i], b[j], s[i][j]);
        }

        // online softmax (row groups are 16-lane contiguous -> shfl_xor<=8 stays in-group)
        #pragma unroll
        for (int i = 0; i < 4; i++) {
            #pragma unroll
            for (int j = 0; j < 4; j++) s[i][j] *= SCALE;
            float rm = fmaxf(fmaxf(s[i][0], s[i][1]), fmaxf(s[i][2], s[i][3]));
            #pragma unroll
            for (int off = 8; off; off >>= 1)
                rm = fmaxf(rm, __shfl_xor_sync(0xffffffffu, rm, off));
            float nm = fmaxf(m[i], rm);
            float corr = __expf(m[i] - nm);
            float rs = 0.f;
            #pragma unroll
            for (int j = 0; j < 4; j++) {
                float p = __expf(s[i][j] - nm);
                s[i][j] = p;
                rs += p;
            }
            #pragma unroll
            for (int off = 8; off; off >>= 1)
                rs += __shfl_xor_sync(0xffffffffu, rs, off);
            l[i] = l[i] * corr + rs;
            m[i] = nm;
            #pragma unroll
            for (int j = 0; j < 4; j++) o[i][j] *= corr;
        }

        __syncthreads();                 // everyone done reading KsT
        #pragma unroll
        for (int i = 0; i < 4; i++)      // P tile overwrites K buffer (row-major [r][c])
            *(float4*)&KsT[(ty << 2) + i][tx << 2] = *(float4*)&s[i][0];
        __syncthreads();

        // O += P @ V
        #pragma unroll
        for (int k = 0; k < 64; k++) {
            float pa[4], vb[4];
            #pragma unroll
            for (int i = 0; i < 4; i++) pa[i] = KsT[(ty << 2) + i][k];
            *(float4*)vb = *(float4*)&Vs[k][tx << 2];
            #pragma unroll
            for (int i = 0; i < 4; i++)
                #pragma unroll
                for (int j = 0; j < 4; j++)
                    o[i][j] = fmaf(pa[i], vb[j], o[i][j]);
        }
        __syncthreads();                 // before next tile overwrites KsT/Vs
    }

    int b = bh >> 3, h = bh & 7;
    #pragma unroll
    for (int i = 0; i < 4; i++) {
        float inv = 1.f / l[i];
        int r = n0 + (ty << 2) + i;
        float4 ov;
        ov.x = o[i][0] * inv;
        ov.y = o[i][1] * inv;
        ov.z = o[i][2] * inv;
        ov.w = o[i][3] * inv;
        *(float4*)&AO[(b * SEQ + r) * DIMW + (h << 6) + (tx << 2)] = ov;
    }
}

// ---------------- launch ----------------------------------------------------
extern "C" void kernel_launch(void* const* d_in, const int* in_sizes, int n_in,
                              void* d_out, int out_size)
{
    const float* x   = (const float*)d_in[0];
    const float* ctx = (const float*)d_in[1];
    const float* Wq  = (const float*)d_in[2];
    const float* Wk  = (const float*)d_in[3];
    const float* Wv  = (const float*)d_in[4];
    const float* Wo  = (const float*)d_in[5];
    const float* bo  = (const float*)d_in[6];
    float* out = (float*)d_out;

    float *qt, *kt, *v, *ao;
    cudaGetSymbolAddress((void**)&qt, g_Qt);
    cudaGetSymbolAddress((void**)&kt, g_Kt);
    cudaGetSymbolAddress((void**)&v,  g_V);
    cudaGetSymbolAddress((void**)&ao, g_AO);

    const int attn_smem = 3 * 64 * 68 * sizeof(float);   // 52224 B
    cudaFuncSetAttribute(attn_kernel, cudaFuncAttributeMaxDynamicSharedMemorySize,
                         attn_smem);

    dim3 gg(ROWS_TOTAL / 64, DIMW / 64);     // 128 x 8

    gemm512k<<<gg, 256>>>(x,   Wq, qt, nullptr, MODE_T);
    gemm512k<<<gg, 256>>>(ctx, Wk, kt, nullptr, MODE_T);
    gemm512k<<<gg, 256>>>(ctx, Wv, v,  nullptr, MODE_V);

    attn_kernel<<<dim3(SEQ / 64, BATCH * HEADS), 256, attn_smem>>>(qt, kt, v, ao);

    gemm512k<<<gg, 256>>>(ao, Wo, out, bo, MODE_P);
}